// round 2
// baseline (speedup 1.0000x reference)
#include <cuda_runtime.h>
#include <cuda_bf16.h>

#define N_NODES 50000

// Scratch (device globals — no allocation allowed)
__device__ float g_agg[(size_t)N_NODES * 256];
__device__ float g_h[(size_t)N_NODES * 256];

// ---------------------------------------------------------------------------
// Zero-fill (float4 vectorized)
// ---------------------------------------------------------------------------
__global__ void zero_kernel(float* __restrict__ p, int n4) {
    int i = blockIdx.x * blockDim.x + threadIdx.x;
    if (i < n4) reinterpret_cast<float4*>(p)[i] = make_float4(0.f, 0.f, 0.f, 0.f);
}

// ---------------------------------------------------------------------------
// Edge scatter: agg[dst] += feat[src], F floats per edge.
// Consecutive threads cover consecutive 16B chunks of one edge's row:
// fully coalesced gather loads and coalesced atomic groups.
// Edge indices are int32 (harness narrows the reference's int64).
// ---------------------------------------------------------------------------
template <int F>
__global__ void scatter_add_kernel(const float* __restrict__ feat,
                                   float* __restrict__ agg,
                                   const int* __restrict__ srcI,
                                   const int* __restrict__ dstI,
                                   int E) {
    int gid = blockIdx.x * blockDim.x + threadIdx.x;
    constexpr int G = F / 4;          // 16B chunks per edge
    int e = gid / G;
    if (e >= E) return;
    int c = (gid - e * G) * 4;
    int s = srcI[e];
    int d = dstI[e];
    float4 v = *reinterpret_cast<const float4*>(feat + (size_t)s * F + c);
    float* p = agg + (size_t)d * F + c;
    atomicAdd(p + 0, v.x);            // unused return -> RED.E.ADD.F32
    atomicAdd(p + 1, v.y);
    atomicAdd(p + 2, v.z);
    atomicAdd(p + 3, v.w);
}

// ---------------------------------------------------------------------------
// C[N,256] = relu(A[N,K] @ B[K,256] + bias)
// 64x64 block tile, BK=16, 256 threads, 4x4 per-thread microtile.
// ---------------------------------------------------------------------------
template <int K>
__global__ __launch_bounds__(256)
void gemm_bias_relu(const float* __restrict__ A,
                    const float* __restrict__ B,
                    const float* __restrict__ bias,
                    float* __restrict__ C, int N) {
    constexpr int BM = 64, BN = 64, BK = 16;
    __shared__ float As[BK][BM + 1];   // +1 pad: kill store bank conflicts
    __shared__ float Bs[BK][BN];

    const int block_row = blockIdx.x * BM;
    const int block_col = blockIdx.y * BN;
    const int tid = threadIdx.x;
    const int tx = tid & 15;           // 0..15 -> N
    const int ty = tid >> 4;           // 0..15 -> M

    float acc[4][4] = {};

    for (int kk = 0; kk < K; kk += BK) {
        // Load A tile 64x16 (row-major [N,K]); store transposed As[k][m]
        {
            int m = tid >> 2;              // 0..63
            int k4 = (tid & 3) * 4;        // 0,4,8,12
            int row = block_row + m;
            float4 a = make_float4(0.f, 0.f, 0.f, 0.f);
            if (row < N)
                a = *reinterpret_cast<const float4*>(A + (size_t)row * K + kk + k4);
            As[k4 + 0][m] = a.x;
            As[k4 + 1][m] = a.y;
            As[k4 + 2][m] = a.z;
            As[k4 + 3][m] = a.w;
        }
        // Load B tile 16x64 (row-major [K,256])
        {
            int k = tid >> 4;              // 0..15
            int n4 = (tid & 15) * 4;       // 0..60
            float4 b = *reinterpret_cast<const float4*>(
                B + (size_t)(kk + k) * 256 + block_col + n4);
            *reinterpret_cast<float4*>(&Bs[k][n4]) = b;
        }
        __syncthreads();

        #pragma unroll
        for (int k = 0; k < BK; k++) {
            float a[4], b[4];
            #pragma unroll
            for (int i = 0; i < 4; i++) a[i] = As[k][ty * 4 + i];
            #pragma unroll
            for (int j = 0; j < 4; j++) b[j] = Bs[k][tx * 4 + j];
            #pragma unroll
            for (int i = 0; i < 4; i++)
                #pragma unroll
                for (int j = 0; j < 4; j++)
                    acc[i][j] += a[i] * b[j];
        }
        __syncthreads();
    }

    // Epilogue: bias + relu
    #pragma unroll
    for (int i = 0; i < 4; i++) {
        int row = block_row + ty * 4 + i;
        if (row < N) {
            float4 r;
            float bx = bias[block_col + tx * 4 + 0];
            float by = bias[block_col + tx * 4 + 1];
            float bz = bias[block_col + tx * 4 + 2];
            float bw = bias[block_col + tx * 4 + 3];
            r.x = fmaxf(acc[i][0] + bx, 0.f);
            r.y = fmaxf(acc[i][1] + by, 0.f);
            r.z = fmaxf(acc[i][2] + bz, 0.f);
            r.w = fmaxf(acc[i][3] + bw, 0.f);
            *reinterpret_cast<float4*>(C + (size_t)row * 256 + block_col + tx * 4) = r;
        }
    }
}

// ---------------------------------------------------------------------------
// Launch: per layer -> zero agg, scatter-first (A h), then GEMM+bias+relu.
// Uses (A h) W == A (h W) to halve layer-1 scatter width.
// ---------------------------------------------------------------------------
extern "C" void kernel_launch(void* const* d_in, const int* in_sizes, int n_in,
                              void* d_out, int out_size) {
    const float* x   = (const float*)d_in[0];
    const int*   ei  = (const int*)d_in[1];
    const float* W1  = (const float*)d_in[2];
    const float* b1  = (const float*)d_in[3];
    const float* W2  = (const float*)d_in[4];
    const float* b2  = (const float*)d_in[5];
    const float* W3  = (const float*)d_in[6];
    const float* b3  = (const float*)d_in[7];
    float*       out = (float*)d_out;

    const int E = in_sizes[1] / 2;
    const int* srcI = ei;
    const int* dstI = ei + E;

    float *agg, *h;
    cudaGetSymbolAddress((void**)&agg, g_agg);
    cudaGetSymbolAddress((void**)&h, g_h);

    dim3 ggrid((N_NODES + 63) / 64, 4);

    // ---- Layer 1: aggregate x (128-wide), then GEMM K=128 ----
    {
        int n4 = N_NODES * 128 / 4;
        zero_kernel<<<(n4 + 255) / 256, 256>>>(agg, n4);
        int T = E * (128 / 4);
        scatter_add_kernel<128><<<(T + 255) / 256, 256>>>(x, agg, srcI, dstI, E);
        gemm_bias_relu<128><<<ggrid, 256>>>(agg, W1, b1, h, N_NODES);
    }
    // ---- Layer 2 ----
    {
        int n4 = N_NODES * 256 / 4;
        zero_kernel<<<(n4 + 255) / 256, 256>>>(agg, n4);
        int T = E * (256 / 4);
        scatter_add_kernel<256><<<(T + 255) / 256, 256>>>(h, agg, srcI, dstI, E);
        gemm_bias_relu<256><<<ggrid, 256>>>(agg, W2, b2, h, N_NODES);
    }
    // ---- Layer 3 ----
    {
        int n4 = N_NODES * 256 / 4;
        zero_kernel<<<(n4 + 255) / 256, 256>>>(agg, n4);
        int T = E * (256 / 4);
        scatter_add_kernel<256><<<(T + 255) / 256, 256>>>(h, agg, srcI, dstI, E);
        gemm_bias_relu<256><<<ggrid, 256>>>(agg, W3, b3, out, N_NODES);
    }
}

// round 3
// speedup vs baseline: 2.5988x; 2.5988x over previous
#include <cuda_runtime.h>
#include <cuda_bf16.h>

#define N_NODES 50000
#define E_MAX   1000000

// ---- device-global scratch (no allocation allowed) ----
__device__ float g_agg[(size_t)N_NODES * 256];
__device__ float g_h[(size_t)N_NODES * 256];
__device__ int   g_deg[N_NODES];
__device__ int   g_cur[N_NODES];
__device__ int   g_rs[N_NODES + 1];
__device__ int   g_csr[E_MAX];

// ---------------------------------------------------------------------------
// packed fp32x2 FMA (sm_103a FFMA2 — only reachable via PTX)
// ---------------------------------------------------------------------------
#define FFMA2(c, a, b) \
    asm("fma.rn.f32x2 %0, %1, %2, %0;" : "+l"(c) : "l"(a), "l"(b))
#define DUP2(d, f) \
    asm("mov.b64 %0, {%1, %1};" : "=l"(d) : "f"(f))

// ---------------------------------------------------------------------------
// CSR build: histogram -> scan -> fill
// ---------------------------------------------------------------------------
__global__ void zero_int_kernel(int* __restrict__ p, int n) {
    int i = blockIdx.x * blockDim.x + threadIdx.x;
    if (i < n) p[i] = 0;
}

__global__ void hist_kernel(const int* __restrict__ dst, int* __restrict__ deg, int E) {
    int e = blockIdx.x * blockDim.x + threadIdx.x;
    if (e < E) atomicAdd(&deg[dst[e]], 1);
}

// Single block, 1024 threads: exclusive scan of deg -> row_start (+cursor copy)
__global__ __launch_bounds__(1024)
void scan_kernel(const int* __restrict__ deg, int* __restrict__ row_start,
                 int* __restrict__ cursor) {
    __shared__ int sums[1024];
    const int t = threadIdx.x;
    const int CH = (N_NODES + 1023) / 1024;
    const int base = t * CH;

    int local = 0;
    for (int i = 0; i < CH; i++) {
        int idx = base + i;
        if (idx < N_NODES) local += deg[idx];
    }
    sums[t] = local;
    __syncthreads();
    for (int off = 1; off < 1024; off <<= 1) {
        int v = (t >= off) ? sums[t - off] : 0;
        __syncthreads();
        sums[t] += v;
        __syncthreads();
    }
    int prefix = sums[t] - local;   // exclusive
    for (int i = 0; i < CH; i++) {
        int idx = base + i;
        if (idx < N_NODES) {
            row_start[idx] = prefix;
            cursor[idx] = prefix;
            prefix += deg[idx];
        }
    }
    if (t == 1023) row_start[N_NODES] = sums[1023];
}

__global__ void fill_kernel(const int* __restrict__ src, const int* __restrict__ dst,
                            int* __restrict__ cursor, int* __restrict__ csr, int E) {
    int e = blockIdx.x * blockDim.x + threadIdx.x;
    if (e >= E) return;
    int pos = atomicAdd(&cursor[dst[e]], 1);
    csr[pos] = src[e];
}

// ---------------------------------------------------------------------------
// Gather-aggregate (no atomics): out[i] = sum_{s in N(i)} feat[s]
// F=128: 1 warp/node; F=256: 2 warps/node (128-float chunks).
// ---------------------------------------------------------------------------
__global__ void aggregate128(const float* __restrict__ feat, float* __restrict__ out,
                             const int* __restrict__ row_start,
                             const int* __restrict__ csr) {
    int w = (blockIdx.x * blockDim.x + threadIdx.x) >> 5;
    int lane = threadIdx.x & 31;
    if (w >= N_NODES) return;
    int beg = row_start[w], end = row_start[w + 1];
    const int col = lane * 4;
    float4 acc = make_float4(0.f, 0.f, 0.f, 0.f);
    int j = beg;
    for (; j + 4 <= end; j += 4) {
        int s0 = csr[j], s1 = csr[j + 1], s2 = csr[j + 2], s3 = csr[j + 3];
        float4 v0 = *reinterpret_cast<const float4*>(feat + (size_t)s0 * 128 + col);
        float4 v1 = *reinterpret_cast<const float4*>(feat + (size_t)s1 * 128 + col);
        float4 v2 = *reinterpret_cast<const float4*>(feat + (size_t)s2 * 128 + col);
        float4 v3 = *reinterpret_cast<const float4*>(feat + (size_t)s3 * 128 + col);
        acc.x += v0.x + v1.x + v2.x + v3.x;
        acc.y += v0.y + v1.y + v2.y + v3.y;
        acc.z += v0.z + v1.z + v2.z + v3.z;
        acc.w += v0.w + v1.w + v2.w + v3.w;
    }
    for (; j < end; j++) {
        int s = csr[j];
        float4 v = *reinterpret_cast<const float4*>(feat + (size_t)s * 128 + col);
        acc.x += v.x; acc.y += v.y; acc.z += v.z; acc.w += v.w;
    }
    *reinterpret_cast<float4*>(out + (size_t)w * 128 + col) = acc;
}

__global__ void aggregate256(const float* __restrict__ feat, float* __restrict__ out,
                             const int* __restrict__ row_start,
                             const int* __restrict__ csr) {
    int w = (blockIdx.x * blockDim.x + threadIdx.x) >> 5;
    int lane = threadIdx.x & 31;
    int node = w >> 1;
    int chunk = w & 1;
    if (node >= N_NODES) return;
    int beg = row_start[node], end = row_start[node + 1];
    const int col = chunk * 128 + lane * 4;
    float4 acc = make_float4(0.f, 0.f, 0.f, 0.f);
    int j = beg;
    for (; j + 4 <= end; j += 4) {
        int s0 = csr[j], s1 = csr[j + 1], s2 = csr[j + 2], s3 = csr[j + 3];
        float4 v0 = *reinterpret_cast<const float4*>(feat + (size_t)s0 * 256 + col);
        float4 v1 = *reinterpret_cast<const float4*>(feat + (size_t)s1 * 256 + col);
        float4 v2 = *reinterpret_cast<const float4*>(feat + (size_t)s2 * 256 + col);
        float4 v3 = *reinterpret_cast<const float4*>(feat + (size_t)s3 * 256 + col);
        acc.x += v0.x + v1.x + v2.x + v3.x;
        acc.y += v0.y + v1.y + v2.y + v3.y;
        acc.z += v0.z + v1.z + v2.z + v3.z;
        acc.w += v0.w + v1.w + v2.w + v3.w;
    }
    for (; j < end; j++) {
        int s = csr[j];
        float4 v = *reinterpret_cast<const float4*>(feat + (size_t)s * 256 + col);
        acc.x += v.x; acc.y += v.y; acc.z += v.z; acc.w += v.w;
    }
    *reinterpret_cast<float4*>(out + (size_t)node * 256 + col) = acc;
}

// ---------------------------------------------------------------------------
// C[N,256] = relu(A[N,K] @ B[K,256] + bias)
// 128x128 tile, BK=16, 256 threads, 8x8 microtile via packed f32x2 FMA.
// ---------------------------------------------------------------------------
template <int K>
__global__ __launch_bounds__(256, 2)
void gemm_bias_relu(const float* __restrict__ A, const float* __restrict__ B,
                    const float* __restrict__ bias, float* __restrict__ C, int N) {
    constexpr int BM = 128, BN = 128, BK = 16;
    __shared__ float As[BK][BM + 4];   // +4: keep 16B align, shift banks per k-row
    __shared__ float Bs[BK][BN];

    const int brow = blockIdx.x * BM;
    const int bcol = blockIdx.y * BN;
    const int tid = threadIdx.x;
    const int tx = tid & 15;           // n
    const int ty = tid >> 4;           // m

    unsigned long long acc[8][4];
    #pragma unroll
    for (int i = 0; i < 8; i++)
        #pragma unroll
        for (int j = 0; j < 4; j++) acc[i][j] = 0ull;

    for (int kk = 0; kk < K; kk += BK) {
        // A tile 128x16, store transposed As[k][m]
        #pragma unroll
        for (int l = 0; l < 2; l++) {
            int idx = tid + l * 256;
            int r = idx >> 2;
            int k4 = (idx & 3) * 4;
            int row = brow + r;
            float4 a = make_float4(0.f, 0.f, 0.f, 0.f);
            if (row < N)
                a = *reinterpret_cast<const float4*>(A + (size_t)row * K + kk + k4);
            As[k4 + 0][r] = a.x;
            As[k4 + 1][r] = a.y;
            As[k4 + 2][r] = a.z;
            As[k4 + 3][r] = a.w;
        }
        // B tile 16x128
        #pragma unroll
        for (int l = 0; l < 2; l++) {
            int idx = tid + l * 256;
            int k = idx >> 5;
            int n4 = (idx & 31) * 4;
            *reinterpret_cast<float4*>(&Bs[k][n4]) =
                *reinterpret_cast<const float4*>(B + (size_t)(kk + k) * 256 + bcol + n4);
        }
        __syncthreads();

        #pragma unroll
        for (int k = 0; k < BK; k++) {
            const float4 a0 = *reinterpret_cast<const float4*>(&As[k][ty * 8]);
            const float4 a1 = *reinterpret_cast<const float4*>(&As[k][ty * 8 + 4]);
            const ulonglong2 bb0 = *reinterpret_cast<const ulonglong2*>(&Bs[k][tx * 8]);
            const ulonglong2 bb1 = *reinterpret_cast<const ulonglong2*>(&Bs[k][tx * 8 + 4]);
            unsigned long long b2[4] = {bb0.x, bb0.y, bb1.x, bb1.y};
            float af[8] = {a0.x, a0.y, a0.z, a0.w, a1.x, a1.y, a1.z, a1.w};
            #pragma unroll
            for (int i = 0; i < 8; i++) {
                unsigned long long a2;
                DUP2(a2, af[i]);
                #pragma unroll
                for (int jp = 0; jp < 4; jp++)
                    FFMA2(acc[i][jp], a2, b2[jp]);
            }
        }
        __syncthreads();
    }

    // Epilogue: bias + relu (bias vals hoisted)
    float bv[8];
    #pragma unroll
    for (int j = 0; j < 8; j++) bv[j] = bias[bcol + tx * 8 + j];

    #pragma unroll
    for (int i = 0; i < 8; i++) {
        int row = brow + ty * 8 + i;
        if (row >= N) continue;
        float o[8];
        #pragma unroll
        for (int jp = 0; jp < 4; jp++) {
            float2 v = *reinterpret_cast<float2*>(&acc[i][jp]);
            o[jp * 2 + 0] = fmaxf(v.x + bv[jp * 2 + 0], 0.f);
            o[jp * 2 + 1] = fmaxf(v.y + bv[jp * 2 + 1], 0.f);
        }
        float4* p = reinterpret_cast<float4*>(C + (size_t)row * 256 + bcol + tx * 8);
        p[0] = make_float4(o[0], o[1], o[2], o[3]);
        p[1] = make_float4(o[4], o[5], o[6], o[7]);
    }
}

// ---------------------------------------------------------------------------
extern "C" void kernel_launch(void* const* d_in, const int* in_sizes, int n_in,
                              void* d_out, int out_size) {
    const float* x   = (const float*)d_in[0];
    const int*   ei  = (const int*)d_in[1];
    const float* W1  = (const float*)d_in[2];
    const float* b1  = (const float*)d_in[3];
    const float* W2  = (const float*)d_in[4];
    const float* b2  = (const float*)d_in[5];
    const float* W3  = (const float*)d_in[6];
    const float* b3  = (const float*)d_in[7];
    float*       out = (float*)d_out;

    const int E = in_sizes[1] / 2;
    const int* srcI = ei;
    const int* dstI = ei + E;

    float *agg, *h;
    int *deg, *cur, *rs, *csr;
    cudaGetSymbolAddress((void**)&agg, g_agg);
    cudaGetSymbolAddress((void**)&h,   g_h);
    cudaGetSymbolAddress((void**)&deg, g_deg);
    cudaGetSymbolAddress((void**)&cur, g_cur);
    cudaGetSymbolAddress((void**)&rs,  g_rs);
    cudaGetSymbolAddress((void**)&csr, g_csr);

    // ---- CSR build (by dst) ----
    zero_int_kernel<<<(N_NODES + 255) / 256, 256>>>(deg, N_NODES);
    hist_kernel<<<(E + 255) / 256, 256>>>(dstI, deg, E);
    scan_kernel<<<1, 1024>>>(deg, rs, cur);
    fill_kernel<<<(E + 255) / 256, 256>>>(srcI, dstI, cur, csr, E);

    dim3 ggrid((N_NODES + 127) / 128, 2);

    // ---- Layer 1: aggregate x (128-wide), GEMM K=128 ----
    {
        int warps = N_NODES;                       // 1 warp/node
        aggregate128<<<(warps * 32 + 255) / 256, 256>>>(x, agg, rs, csr);
        gemm_bias_relu<128><<<ggrid, 256>>>(agg, W1, b1, h, N_NODES);
    }
    // ---- Layer 2 ----
    {
        int warps = N_NODES * 2;                   // 2 warps/node
        aggregate256<<<(warps * 32 + 255) / 256, 256>>>(h, agg, rs, csr);
        gemm_bias_relu<256><<<ggrid, 256>>>(agg, W2, b2, h, N_NODES);
    }
    // ---- Layer 3 ----
    {
        int warps = N_NODES * 2;
        aggregate256<<<(warps * 32 + 255) / 256, 256>>>(h, agg, rs, csr);
        gemm_bias_relu<256><<<ggrid, 256>>>(agg, W3, b3, out, N_NODES);
    }
}

// round 4
// speedup vs baseline: 2.6038x; 1.0019x over previous
#include <cuda_runtime.h>
#include <cuda_bf16.h>

#define N_NODES 50000
#define E_MAX   1000000

// ---- device-global scratch (no allocation allowed) ----
__device__ float g_agg[(size_t)N_NODES * 256];
__device__ float g_h[(size_t)N_NODES * 256];
__device__ int   g_deg[N_NODES];
__device__ int   g_cur[N_NODES];
__device__ int   g_rs[N_NODES + 1];
__device__ int   g_csr[E_MAX];

// ---------------------------------------------------------------------------
// packed fp32x2 FMA (sm_103a FFMA2 — only reachable via PTX)
// ---------------------------------------------------------------------------
#define FFMA2(c, a, b) \
    asm("fma.rn.f32x2 %0, %1, %2, %0;" : "+l"(c) : "l"(a), "l"(b))
#define DUP2(d, f) \
    asm("mov.b64 %0, {%1, %1};" : "=l"(d) : "f"(f))

// ---------------------------------------------------------------------------
// CSR build: histogram -> scan -> fill
// ---------------------------------------------------------------------------
__global__ void zero_int_kernel(int* __restrict__ p, int n) {
    int i = blockIdx.x * blockDim.x + threadIdx.x;
    if (i < n) p[i] = 0;
}

__global__ void hist_kernel(const int* __restrict__ dst, int* __restrict__ deg, int E) {
    int e = blockIdx.x * blockDim.x + threadIdx.x;
    if (e < E) atomicAdd(&deg[dst[e]], 1);
}

// Single block, 1024 threads: exclusive scan of deg -> row_start (+cursor copy)
__global__ __launch_bounds__(1024)
void scan_kernel(const int* __restrict__ deg, int* __restrict__ row_start,
                 int* __restrict__ cursor) {
    __shared__ int sums[1024];
    const int t = threadIdx.x;
    const int CH = (N_NODES + 1023) / 1024;
    const int base = t * CH;

    int local = 0;
    for (int i = 0; i < CH; i++) {
        int idx = base + i;
        if (idx < N_NODES) local += deg[idx];
    }
    sums[t] = local;
    __syncthreads();
    for (int off = 1; off < 1024; off <<= 1) {
        int v = (t >= off) ? sums[t - off] : 0;
        __syncthreads();
        sums[t] += v;
        __syncthreads();
    }
    int prefix = sums[t] - local;   // exclusive
    for (int i = 0; i < CH; i++) {
        int idx = base + i;
        if (idx < N_NODES) {
            row_start[idx] = prefix;
            cursor[idx] = prefix;
            prefix += deg[idx];
        }
    }
    if (t == 1023) row_start[N_NODES] = sums[1023];
}

__global__ void fill_kernel(const int* __restrict__ src, const int* __restrict__ dst,
                            int* __restrict__ cursor, int* __restrict__ csr, int E) {
    int e = blockIdx.x * blockDim.x + threadIdx.x;
    if (e >= E) return;
    int pos = atomicAdd(&cursor[dst[e]], 1);
    csr[pos] = src[e];
}

// ---------------------------------------------------------------------------
// Gather-aggregate (no atomics): out[i] = sum_{s in N(i)} feat[s]
// F=128: 1 warp/node; F=256: 2 warps/node (128-float chunks).
// ---------------------------------------------------------------------------
__global__ void aggregate128(const float* __restrict__ feat, float* __restrict__ out,
                             const int* __restrict__ row_start,
                             const int* __restrict__ csr) {
    int w = (blockIdx.x * blockDim.x + threadIdx.x) >> 5;
    int lane = threadIdx.x & 31;
    if (w >= N_NODES) return;
    int beg = row_start[w], end = row_start[w + 1];
    const int col = lane * 4;
    float4 acc = make_float4(0.f, 0.f, 0.f, 0.f);
    int j = beg;
    for (; j + 4 <= end; j += 4) {
        int s0 = csr[j], s1 = csr[j + 1], s2 = csr[j + 2], s3 = csr[j + 3];
        float4 v0 = *reinterpret_cast<const float4*>(feat + (size_t)s0 * 128 + col);
        float4 v1 = *reinterpret_cast<const float4*>(feat + (size_t)s1 * 128 + col);
        float4 v2 = *reinterpret_cast<const float4*>(feat + (size_t)s2 * 128 + col);
        float4 v3 = *reinterpret_cast<const float4*>(feat + (size_t)s3 * 128 + col);
        acc.x += v0.x + v1.x + v2.x + v3.x;
        acc.y += v0.y + v1.y + v2.y + v3.y;
        acc.z += v0.z + v1.z + v2.z + v3.z;
        acc.w += v0.w + v1.w + v2.w + v3.w;
    }
    for (; j < end; j++) {
        int s = csr[j];
        float4 v = *reinterpret_cast<const float4*>(feat + (size_t)s * 128 + col);
        acc.x += v.x; acc.y += v.y; acc.z += v.z; acc.w += v.w;
    }
    *reinterpret_cast<float4*>(out + (size_t)w * 128 + col) = acc;
}

__global__ void aggregate256(const float* __restrict__ feat, float* __restrict__ out,
                             const int* __restrict__ row_start,
                             const int* __restrict__ csr) {
    int w = (blockIdx.x * blockDim.x + threadIdx.x) >> 5;
    int lane = threadIdx.x & 31;
    int node = w >> 1;
    int chunk = w & 1;
    if (node >= N_NODES) return;
    int beg = row_start[node], end = row_start[node + 1];
    const int col = chunk * 128 + lane * 4;
    float4 acc = make_float4(0.f, 0.f, 0.f, 0.f);
    int j = beg;
    for (; j + 4 <= end; j += 4) {
        int s0 = csr[j], s1 = csr[j + 1], s2 = csr[j + 2], s3 = csr[j + 3];
        float4 v0 = *reinterpret_cast<const float4*>(feat + (size_t)s0 * 256 + col);
        float4 v1 = *reinterpret_cast<const float4*>(feat + (size_t)s1 * 256 + col);
        float4 v2 = *reinterpret_cast<const float4*>(feat + (size_t)s2 * 256 + col);
        float4 v3 = *reinterpret_cast<const float4*>(feat + (size_t)s3 * 256 + col);
        acc.x += v0.x + v1.x + v2.x + v3.x;
        acc.y += v0.y + v1.y + v2.y + v3.y;
        acc.z += v0.z + v1.z + v2.z + v3.z;
        acc.w += v0.w + v1.w + v2.w + v3.w;
    }
    for (; j < end; j++) {
        int s = csr[j];
        float4 v = *reinterpret_cast<const float4*>(feat + (size_t)s * 256 + col);
        acc.x += v.x; acc.y += v.y; acc.z += v.z; acc.w += v.w;
    }
    *reinterpret_cast<float4*>(out + (size_t)node * 256 + col) = acc;
}

// ---------------------------------------------------------------------------
// C[N,256] = relu(A[N,K] @ B[K,256] + bias)
// 128x128 tile, BK=16, 256 threads, 8x8 microtile via packed f32x2 FMA.
// ---------------------------------------------------------------------------
template <int K>
__global__ __launch_bounds__(256, 2)
void gemm_bias_relu(const float* __restrict__ A, const float* __restrict__ B,
                    const float* __restrict__ bias, float* __restrict__ C, int N) {
    constexpr int BM = 128, BN = 128, BK = 16;
    __shared__ float As[BK][BM + 4];   // +4: keep 16B align, shift banks per k-row
    __shared__ float Bs[BK][BN];

    const int brow = blockIdx.x * BM;
    const int bcol = blockIdx.y * BN;
    const int tid = threadIdx.x;
    const int tx = tid & 15;           // n
    const int ty = tid >> 4;           // m

    unsigned long long acc[8][4];
    #pragma unroll
    for (int i = 0; i < 8; i++)
        #pragma unroll
        for (int j = 0; j < 4; j++) acc[i][j] = 0ull;

    for (int kk = 0; kk < K; kk += BK) {
        // A tile 128x16, store transposed As[k][m]
        #pragma unroll
        for (int l = 0; l < 2; l++) {
            int idx = tid + l * 256;
            int r = idx >> 2;
            int k4 = (idx & 3) * 4;
            int row = brow + r;
            float4 a = make_float4(0.f, 0.f, 0.f, 0.f);
            if (row < N)
                a = *reinterpret_cast<const float4*>(A + (size_t)row * K + kk + k4);
            As[k4 + 0][r] = a.x;
            As[k4 + 1][r] = a.y;
            As[k4 + 2][r] = a.z;
            As[k4 + 3][r] = a.w;
        }
        // B tile 16x128
        #pragma unroll
        for (int l = 0; l < 2; l++) {
            int idx = tid + l * 256;
            int k = idx >> 5;
            int n4 = (idx & 31) * 4;
            *reinterpret_cast<float4*>(&Bs[k][n4]) =
                *reinterpret_cast<const float4*>(B + (size_t)(kk + k) * 256 + bcol + n4);
        }
        __syncthreads();

        #pragma unroll
        for (int k = 0; k < BK; k++) {
            const float4 a0 = *reinterpret_cast<const float4*>(&As[k][ty * 8]);
            const float4 a1 = *reinterpret_cast<const float4*>(&As[k][ty * 8 + 4]);
            const ulonglong2 bb0 = *reinterpret_cast<const ulonglong2*>(&Bs[k][tx * 8]);
            const ulonglong2 bb1 = *reinterpret_cast<const ulonglong2*>(&Bs[k][tx * 8 + 4]);
            unsigned long long b2[4] = {bb0.x, bb0.y, bb1.x, bb1.y};
            float af[8] = {a0.x, a0.y, a0.z, a0.w, a1.x, a1.y, a1.z, a1.w};
            #pragma unroll
            for (int i = 0; i < 8; i++) {
                unsigned long long a2;
                DUP2(a2, af[i]);
                #pragma unroll
                for (int jp = 0; jp < 4; jp++)
                    FFMA2(acc[i][jp], a2, b2[jp]);
            }
        }
        __syncthreads();
    }

    // Epilogue: bias + relu (bias vals hoisted)
    float bv[8];
    #pragma unroll
    for (int j = 0; j < 8; j++) bv[j] = bias[bcol + tx * 8 + j];

    #pragma unroll
    for (int i = 0; i < 8; i++) {
        int row = brow + ty * 8 + i;
        if (row >= N) continue;
        float o[8];
        #pragma unroll
        for (int jp = 0; jp < 4; jp++) {
            float2 v = *reinterpret_cast<float2*>(&acc[i][jp]);
            o[jp * 2 + 0] = fmaxf(v.x + bv[jp * 2 + 0], 0.f);
            o[jp * 2 + 1] = fmaxf(v.y + bv[jp * 2 + 1], 0.f);
        }
        float4* p = reinterpret_cast<float4*>(C + (size_t)row * 256 + bcol + tx * 8);
        p[0] = make_float4(o[0], o[1], o[2], o[3]);
        p[1] = make_float4(o[4], o[5], o[6], o[7]);
    }
}

// ---------------------------------------------------------------------------
extern "C" void kernel_launch(void* const* d_in, const int* in_sizes, int n_in,
                              void* d_out, int out_size) {
    const float* x   = (const float*)d_in[0];
    const int*   ei  = (const int*)d_in[1];
    const float* W1  = (const float*)d_in[2];
    const float* b1  = (const float*)d_in[3];
    const float* W2  = (const float*)d_in[4];
    const float* b2  = (const float*)d_in[5];
    const float* W3  = (const float*)d_in[6];
    const float* b3  = (const float*)d_in[7];
    float*       out = (float*)d_out;

    const int E = in_sizes[1] / 2;
    const int* srcI = ei;
    const int* dstI = ei + E;

    float *agg, *h;
    int *deg, *cur, *rs, *csr;
    cudaGetSymbolAddress((void**)&agg, g_agg);
    cudaGetSymbolAddress((void**)&h,   g_h);
    cudaGetSymbolAddress((void**)&deg, g_deg);
    cudaGetSymbolAddress((void**)&cur, g_cur);
    cudaGetSymbolAddress((void**)&rs,  g_rs);
    cudaGetSymbolAddress((void**)&csr, g_csr);

    // ---- CSR build (by dst) ----
    zero_int_kernel<<<(N_NODES + 255) / 256, 256>>>(deg, N_NODES);
    hist_kernel<<<(E + 255) / 256, 256>>>(dstI, deg, E);
    scan_kernel<<<1, 1024>>>(deg, rs, cur);
    fill_kernel<<<(E + 255) / 256, 256>>>(srcI, dstI, cur, csr, E);

    dim3 ggrid((N_NODES + 127) / 128, 2);

    // ---- Layer 1: aggregate x (128-wide), GEMM K=128 ----
    {
        int warps = N_NODES;                       // 1 warp/node
        aggregate128<<<(warps * 32 + 255) / 256, 256>>>(x, agg, rs, csr);
        gemm_bias_relu<128><<<ggrid, 256>>>(agg, W1, b1, h, N_NODES);
    }
    // ---- Layer 2 ----
    {
        int warps = N_NODES * 2;                   // 2 warps/node
        aggregate256<<<(warps * 32 + 255) / 256, 256>>>(h, agg, rs, csr);
        gemm_bias_relu<256><<<ggrid, 256>>>(agg, W2, b2, h, N_NODES);
    }
    // ---- Layer 3 ----
    {
        int warps = N_NODES * 2;
        aggregate256<<<(warps * 32 + 255) / 256, 256>>>(h, agg, rs, csr);
        gemm_bias_relu<256><<<ggrid, 256>>>(agg, W3, b3, out, N_NODES);
    }
}